// round 11
// baseline (speedup 1.0000x reference)
#include <cuda_runtime.h>

#define NQ 16
#define BATCH 512

// Warp-autonomous transfer-matrix evaluation, 1 warp = 1 sample.
// 128 CTAs x 128 threads (1 warp/SMSP, widest wave) — measured optimum.
// All per-step coefficients hoisted into registers; 15-step pure-FMA chain.
__global__ void __launch_bounds__(128, 1) k_expval(const float* __restrict__ x,
                                                   const float* __restrict__ p_,
                                                   float* __restrict__ out) {
    const int lane = threadIdx.x & 31;
    const int b    = (blockIdx.x << 2) + (threadIdx.x >> 5);   // sample

    // ---- per-lane raw constants; both LDGs issued back-to-back (MLP=2) ----
    const float pw = p_[lane];                        // th0 (lane<16) / th1
    const float xw = (lane < 16) ? x[b * NQ + lane] : 0.f;

    float vA, vB, vC, vD, vE;
    {
        float sx, cx; __sincosf(xw, &sx, &cx);
        float sp, cp; __sincosf(pw, &sp, &cp);
        if (lane < 16) {
            vA = cp * cx;   // nd  = cos th0 * cos x
            vB = sp * cx;   // wx2 = sin th0 * cos x
            vC = sx;        // wy2 = sin x
            vD = 0.f; vE = 0.f;
        } else {
            vD = cp; vE = sp;
            vA = 0.f; vB = 0.f; vC = 0.f;
        }
    }

    // ---- chain assignment (validated rounds 7-10) ----
    const int  meff = (lane >= 14) ? 15 : (lane + 1);
    const bool isM0 = (lane == 14);
    const bool isHi = (lane >= 16);

    // ---- hoisted coefficient block: all shuffles + selects up front ----
    float nd[NQ], wx2[NQ], wy2[NQ], al[NQ], be[NQ], m01[NQ];
    #pragma unroll
    for (int w = 1; w < NQ; w++) {
        nd[w]  = __shfl_sync(0xFFFFFFFFu, vA, w);
        wx2[w] = __shfl_sync(0xFFFFFFFFu, vB, w);
        wy2[w] = __shfl_sync(0xFFFFFFFFu, vC, w);
        const float C = __shfl_sync(0xFFFFFFFFu, vD, 16 + w);
        const float S = __shfl_sync(0xFFFFFFFFu, vE, 16 + w);
        const bool sg = (w <= meff);
        al[w]  = sg ? 0.f : 1.f;
        be[w]  = sg ? C   : 0.f;
        m01[w] = sg ? -S  : 0.f;
    }

    // wire-0 constants
    const float nd0  = __shfl_sync(0xFFFFFFFFu, vA, 0);
    const float wx20 = __shfl_sync(0xFFFFFFFFu, vB, 0);
    const float sx0  = __shfl_sync(0xFFFFFFFFu, vC, 0);
    const float C0   = __shfl_sync(0xFFFFFFFFu, vD, 16);
    const float S0   = __shfl_sync(0xFFFFFFFFu, vE, 16);

    // ---- wire-0 init (validated rounds 5-10) ----
    float pA, qA, RA, SA, pB, qB, RB, SB;
    if (isM0) {
        pA = 1.f;        qA = nd0;        RA = 0.f;        SA = 0.f;
        pB = 0.f;        qB = 0.f;        RB = wx20;       SB = sx0;
    } else if (isHi) {
        pA = -S0;        qA = -S0 * nd0;  RA = 0.f;        SA = 0.f;
        pB = 0.f;        qB = 0.f;        RB = C0 * sx0;   SB = -C0 * wx20;
    } else {
        pA = C0 * nd0;   qA = C0;         RA = 0.f;        SA = 0.f;
        pB = 0.f;        qB = 0.f;        RB = -S0 * wx20; SB = -S0 * sx0;
    }

    // ---- wires 1..15: pure-FMA chain ----
    #pragma unroll
    for (int w = 1; w < NQ; w++) {
        const float ndw = nd[w], wxw = wx2[w], wyw = wy2[w];
        const float alw = al[w], bew = be[w], mw = m01[w];
        {   // chain A
            const float hp = fmaf(wxw, RA, pA);
            const float hq = fmaf(ndw, qA, -wyw * SA);
            const float hr = fmaf(wxw, pA, RA);
            const float hs = fmaf(wyw, qA, ndw * SA);
            pA = fmaf(bew, hq, alw * hp);
            qA = fmaf(bew, hp, alw * hq);
            RA = mw * hr;
            SA = mw * hs;
        }
        {   // chain B
            const float hp = fmaf(wxw, RB, pB);
            const float hq = fmaf(ndw, qB, -wyw * SB);
            const float hr = fmaf(wxw, pB, RB);
            const float hs = fmaf(wyw, qB, ndw * SB);
            pB = fmaf(bew, hq, alw * hp);
            qB = fmaf(bew, hp, alw * hq);
            RB = mw * hr;
            SB = mw * hs;
        }
    }

    // ---- readout ----
    const float valA = isM0 ? pA : (isHi ? RA : qA);
    const float valB = isM0 ? RB : (isHi ? -SB : pB);
    float val = valA + valB;

    // combine m=15 halves (lane 15 <- lane 31)
    val += (lane == 15 || lane == 31) ? __shfl_xor_sync(0xFFFFFFFFu, val, 16)
                                      : 0.f;

    if (lane < 16) {
        const int m = (lane < 14) ? (lane + 1) : ((lane == 14) ? 0 : 15);
        out[b * NQ + m] = val;
    }
}

extern "C" void kernel_launch(void* const* d_in, const int* in_sizes, int n_in,
                              void* d_out, int out_size) {
    (void)in_sizes; (void)n_in; (void)out_size;
    const float* x      = (const float*)d_in[0];
    const float* params = (const float*)d_in[1];
    float* out = (float*)d_out;

    k_expval<<<128, 128>>>(x, params, out);
}

// round 12
// speedup vs baseline: 1.0337x; 1.0337x over previous
#include <cuda_runtime.h>

#define NQ 16
#define BATCH 512

// Warp-autonomous transfer-matrix evaluation, 1 warp = 1 sample.
// 128 CTAs x 128 threads (1 warp/SMSP, widest wave) — measured optimum.
// All per-step coefficients hoisted into registers; 15-step pure-FMA chain.
__global__ void __launch_bounds__(128, 1) k_expval(const float* __restrict__ x,
                                                   const float* __restrict__ p_,
                                                   float* __restrict__ out) {
    const int lane = threadIdx.x & 31;
    const int b    = (blockIdx.x << 2) + (threadIdx.x >> 5);   // sample

    // ---- per-lane raw constants; both LDGs issued back-to-back (MLP=2) ----
    const float pw = p_[lane];                        // th0 (lane<16) / th1
    const float xw = (lane < 16) ? x[b * NQ + lane] : 0.f;

    float vA, vB, vC, vD, vE;
    {
        float sx, cx; __sincosf(xw, &sx, &cx);
        float sp, cp; __sincosf(pw, &sp, &cp);
        if (lane < 16) {
            vA = cp * cx;   // nd  = cos th0 * cos x
            vB = sp * cx;   // wx2 = sin th0 * cos x
            vC = sx;        // wy2 = sin x
            vD = 0.f; vE = 0.f;
        } else {
            vD = cp; vE = sp;
            vA = 0.f; vB = 0.f; vC = 0.f;
        }
    }

    // ---- chain assignment (validated rounds 7-10) ----
    const int  meff = (lane >= 14) ? 15 : (lane + 1);
    const bool isM0 = (lane == 14);
    const bool isHi = (lane >= 16);

    // ---- hoisted coefficient block: all shuffles + selects up front ----
    float nd[NQ], wx2[NQ], wy2[NQ], al[NQ], be[NQ], m01[NQ];
    #pragma unroll
    for (int w = 1; w < NQ; w++) {
        nd[w]  = __shfl_sync(0xFFFFFFFFu, vA, w);
        wx2[w] = __shfl_sync(0xFFFFFFFFu, vB, w);
        wy2[w] = __shfl_sync(0xFFFFFFFFu, vC, w);
        const float C = __shfl_sync(0xFFFFFFFFu, vD, 16 + w);
        const float S = __shfl_sync(0xFFFFFFFFu, vE, 16 + w);
        const bool sg = (w <= meff);
        al[w]  = sg ? 0.f : 1.f;
        be[w]  = sg ? C   : 0.f;
        m01[w] = sg ? -S  : 0.f;
    }

    // wire-0 constants
    const float nd0  = __shfl_sync(0xFFFFFFFFu, vA, 0);
    const float wx20 = __shfl_sync(0xFFFFFFFFu, vB, 0);
    const float sx0  = __shfl_sync(0xFFFFFFFFu, vC, 0);
    const float C0   = __shfl_sync(0xFFFFFFFFu, vD, 16);
    const float S0   = __shfl_sync(0xFFFFFFFFu, vE, 16);

    // ---- wire-0 init (validated rounds 5-10) ----
    float pA, qA, RA, SA, pB, qB, RB, SB;
    if (isM0) {
        pA = 1.f;        qA = nd0;        RA = 0.f;        SA = 0.f;
        pB = 0.f;        qB = 0.f;        RB = wx20;       SB = sx0;
    } else if (isHi) {
        pA = -S0;        qA = -S0 * nd0;  RA = 0.f;        SA = 0.f;
        pB = 0.f;        qB = 0.f;        RB = C0 * sx0;   SB = -C0 * wx20;
    } else {
        pA = C0 * nd0;   qA = C0;         RA = 0.f;        SA = 0.f;
        pB = 0.f;        qB = 0.f;        RB = -S0 * wx20; SB = -S0 * sx0;
    }

    // ---- wires 1..15: pure-FMA chain ----
    #pragma unroll
    for (int w = 1; w < NQ; w++) {
        const float ndw = nd[w], wxw = wx2[w], wyw = wy2[w];
        const float alw = al[w], bew = be[w], mw = m01[w];
        {   // chain A
            const float hp = fmaf(wxw, RA, pA);
            const float hq = fmaf(ndw, qA, -wyw * SA);
            const float hr = fmaf(wxw, pA, RA);
            const float hs = fmaf(wyw, qA, ndw * SA);
            pA = fmaf(bew, hq, alw * hp);
            qA = fmaf(bew, hp, alw * hq);
            RA = mw * hr;
            SA = mw * hs;
        }
        {   // chain B
            const float hp = fmaf(wxw, RB, pB);
            const float hq = fmaf(ndw, qB, -wyw * SB);
            const float hr = fmaf(wxw, pB, RB);
            const float hs = fmaf(wyw, qB, ndw * SB);
            pB = fmaf(bew, hq, alw * hp);
            qB = fmaf(bew, hp, alw * hq);
            RB = mw * hr;
            SB = mw * hs;
        }
    }

    // ---- readout ----
    const float valA = isM0 ? pA : (isHi ? RA : qA);
    const float valB = isM0 ? RB : (isHi ? -SB : pB);
    float val = valA + valB;

    // combine m=15 halves (lane 15 <- lane 31)
    val += (lane == 15 || lane == 31) ? __shfl_xor_sync(0xFFFFFFFFu, val, 16)
                                      : 0.f;

    if (lane < 16) {
        const int m = (lane < 14) ? (lane + 1) : ((lane == 14) ? 0 : 15);
        out[b * NQ + m] = val;
    }
}

extern "C" void kernel_launch(void* const* d_in, const int* in_sizes, int n_in,
                              void* d_out, int out_size) {
    (void)in_sizes; (void)n_in; (void)out_size;
    const float* x      = (const float*)d_in[0];
    const float* params = (const float*)d_in[1];
    float* out = (float*)d_out;

    k_expval<<<128, 128>>>(x, params, out);
}

// round 13
// speedup vs baseline: 1.0437x; 1.0097x over previous
#include <cuda_runtime.h>

#define NQ 16
#define BATCH 512

// Warp-autonomous transfer-matrix evaluation, 1 warp = 1 sample.
// 128 CTAs x 128 threads (1 warp/SMSP, widest wave) — measured optimum.
// All per-step coefficients hoisted into registers; 15-step pure-FMA chain.
__global__ void __launch_bounds__(128, 1) k_expval(const float* __restrict__ x,
                                                   const float* __restrict__ p_,
                                                   float* __restrict__ out) {
    const int lane = threadIdx.x & 31;
    const int b    = (blockIdx.x << 2) + (threadIdx.x >> 5);   // sample

    // ---- per-lane raw constants; both LDGs issued back-to-back (MLP=2) ----
    const float pw = p_[lane];                        // th0 (lane<16) / th1
    const float xw = (lane < 16) ? x[b * NQ + lane] : 0.f;

    float vA, vB, vC, vD, vE;
    {
        float sx, cx; __sincosf(xw, &sx, &cx);
        float sp, cp; __sincosf(pw, &sp, &cp);
        if (lane < 16) {
            vA = cp * cx;   // nd  = cos th0 * cos x
            vB = sp * cx;   // wx2 = sin th0 * cos x
            vC = sx;        // wy2 = sin x
            vD = 0.f; vE = 0.f;
        } else {
            vD = cp; vE = sp;
            vA = 0.f; vB = 0.f; vC = 0.f;
        }
    }

    // ---- chain assignment (validated rounds 7-10) ----
    const int  meff = (lane >= 14) ? 15 : (lane + 1);
    const bool isM0 = (lane == 14);
    const bool isHi = (lane >= 16);

    // ---- hoisted coefficient block: all shuffles + selects up front ----
    float nd[NQ], wx2[NQ], wy2[NQ], al[NQ], be[NQ], m01[NQ];
    #pragma unroll
    for (int w = 1; w < NQ; w++) {
        nd[w]  = __shfl_sync(0xFFFFFFFFu, vA, w);
        wx2[w] = __shfl_sync(0xFFFFFFFFu, vB, w);
        wy2[w] = __shfl_sync(0xFFFFFFFFu, vC, w);
        const float C = __shfl_sync(0xFFFFFFFFu, vD, 16 + w);
        const float S = __shfl_sync(0xFFFFFFFFu, vE, 16 + w);
        const bool sg = (w <= meff);
        al[w]  = sg ? 0.f : 1.f;
        be[w]  = sg ? C   : 0.f;
        m01[w] = sg ? -S  : 0.f;
    }

    // wire-0 constants
    const float nd0  = __shfl_sync(0xFFFFFFFFu, vA, 0);
    const float wx20 = __shfl_sync(0xFFFFFFFFu, vB, 0);
    const float sx0  = __shfl_sync(0xFFFFFFFFu, vC, 0);
    const float C0   = __shfl_sync(0xFFFFFFFFu, vD, 16);
    const float S0   = __shfl_sync(0xFFFFFFFFu, vE, 16);

    // ---- wire-0 init (validated rounds 5-10) ----
    float pA, qA, RA, SA, pB, qB, RB, SB;
    if (isM0) {
        pA = 1.f;        qA = nd0;        RA = 0.f;        SA = 0.f;
        pB = 0.f;        qB = 0.f;        RB = wx20;       SB = sx0;
    } else if (isHi) {
        pA = -S0;        qA = -S0 * nd0;  RA = 0.f;        SA = 0.f;
        pB = 0.f;        qB = 0.f;        RB = C0 * sx0;   SB = -C0 * wx20;
    } else {
        pA = C0 * nd0;   qA = C0;         RA = 0.f;        SA = 0.f;
        pB = 0.f;        qB = 0.f;        RB = -S0 * wx20; SB = -S0 * sx0;
    }

    // ---- wires 1..15: pure-FMA chain ----
    #pragma unroll
    for (int w = 1; w < NQ; w++) {
        const float ndw = nd[w], wxw = wx2[w], wyw = wy2[w];
        const float alw = al[w], bew = be[w], mw = m01[w];
        {   // chain A
            const float hp = fmaf(wxw, RA, pA);
            const float hq = fmaf(ndw, qA, -wyw * SA);
            const float hr = fmaf(wxw, pA, RA);
            const float hs = fmaf(wyw, qA, ndw * SA);
            pA = fmaf(bew, hq, alw * hp);
            qA = fmaf(bew, hp, alw * hq);
            RA = mw * hr;
            SA = mw * hs;
        }
        {   // chain B
            const float hp = fmaf(wxw, RB, pB);
            const float hq = fmaf(ndw, qB, -wyw * SB);
            const float hr = fmaf(wxw, pB, RB);
            const float hs = fmaf(wyw, qB, ndw * SB);
            pB = fmaf(bew, hq, alw * hp);
            qB = fmaf(bew, hp, alw * hq);
            RB = mw * hr;
            SB = mw * hs;
        }
    }

    // ---- readout ----
    const float valA = isM0 ? pA : (isHi ? RA : qA);
    const float valB = isM0 ? RB : (isHi ? -SB : pB);
    float val = valA + valB;

    // combine m=15 halves (lane 15 <- lane 31)
    val += (lane == 15 || lane == 31) ? __shfl_xor_sync(0xFFFFFFFFu, val, 16)
                                      : 0.f;

    if (lane < 16) {
        const int m = (lane < 14) ? (lane + 1) : ((lane == 14) ? 0 : 15);
        out[b * NQ + m] = val;
    }
}

extern "C" void kernel_launch(void* const* d_in, const int* in_sizes, int n_in,
                              void* d_out, int out_size) {
    (void)in_sizes; (void)n_in; (void)out_size;
    const float* x      = (const float*)d_in[0];
    const float* params = (const float*)d_in[1];
    float* out = (float*)d_out;

    k_expval<<<128, 128>>>(x, params, out);
}